// round 5
// baseline (speedup 1.0000x reference)
#include <cuda_runtime.h>
#include <math.h>

typedef unsigned long long ull;

// Problem constants
#define SEQ   256
#define BSZ   16
#define HID   512
#define EMB   768
#define VOC   30522
#define TM1   99

// ---------------- scratch (device globals; no allocations) ----------------
__device__ float g_gi_f[SEQ*BSZ*1536];     // encoder fwd gi
__device__ float g_gi_b[SEQ*BSZ*1536];     // encoder bwd gi
__device__ float g_enc_out[BSZ*SEQ*1024];  // [b][s][1024] concat(fwd,bwd)
__device__ float g_hf[HID*BSZ];            // h in hs4 layout: (i>>2)*64 + b*4 + (i&3)
__device__ float g_hb[HID*BSZ];
__device__ float g_hd[HID*BSZ];
__device__ float g_v[1024];                // folded attention vector (enc part)
__device__ float g_c0;                     // folded attention scalar
__device__ float g_ctx2h[BSZ*1024];
__device__ float g_ctx[BSZ*HID];
__device__ float g_ctxgi[BSZ*1536];        // ctx@dec_Wih[:,768:].T + dec_bih
__device__ float g_gid[TM1*BSZ*1536];      // decoder gi
__device__ float g_Hs[TM1*BSZ*HID];        // decoder hidden states row-major [(t*16+b)][512]
__device__ float g_base[BSZ*VOC];          // ctx@out_W[:,512:].T + out_b

// ---------------- f32x2 helpers -------------------------------------------
__device__ __forceinline__ ull fma2(ull a, ull b, ull c) {
    ull d;
    asm("fma.rn.f32x2 %0, %1, %2, %3;" : "=l"(d) : "l"(a), "l"(b), "l"(c));
    return d;
}
__device__ __forceinline__ ull dup2(float x) {
    ull d;
    asm("mov.b64 %0, {%1, %1};" : "=l"(d) : "f"(x));
    return d;
}
__device__ __forceinline__ float hsum2(ull v) {
    float x, y;
    asm("mov.b64 {%0, %1}, %2;" : "=f"(x), "=f"(y) : "l"(v));
    return x + y;
}
__device__ __forceinline__ float2 unp2(ull v) {
    float2 r;
    asm("mov.b64 {%0, %1}, %2;" : "=f"(r.x), "=f"(r.y) : "l"(v));
    return r;
}
union F4U { float4 f; ull u[2]; };

__device__ __forceinline__ float sigmoidf_(float x) { return 1.0f / (1.0f + expf(-x)); }

// ---------------- fold attention: v[k] = comb_W @ attn_W[:, k], c0 ---------
__global__ void fold_kernel(const float* __restrict__ attn_W, const float* __restrict__ attn_b,
                            const float* __restrict__ comb_W, const float* __restrict__ comb_b) {
    int k = blockIdx.x * 256 + threadIdx.x;
    if (k < 1024) {
        float acc = 0.f;
        for (int j = 0; j < 512; j++) acc += comb_W[j] * attn_W[(size_t)j * 1536 + k];
        g_v[k] = acc;
    }
    if (blockIdx.x == 0 && threadIdx.x == 0) {
        float c = comb_b[0];
        for (int j = 0; j < 512; j++) c += comb_W[j] * attn_b[j];
        g_c0 = c;
    }
}

// ---------------- 128x128x32 SGEMM with f32x2 FFMA2: C = A @ W.T -----------
template<int MODE>
__global__ void __launch_bounds__(256) sgemm2(
    const float* __restrict__ Asrc, const float* __restrict__ W, int ldw,
    const float* __restrict__ bias, const int* __restrict__ toks,
    float* __restrict__ Cout, int sel, int M, int N, int K)
{
    const int BM = 128, BN = 128, BK = 32;
    extern __shared__ char smraw[];
    float* As = (float*)smraw;                  // [BK][BM] floats, 16KB
    ull*   Bs = (ull*)(smraw + BK * BM * 4);    // [BK][BN] duplicated pairs, 32KB

    int tid = threadIdx.x;
    int row0 = blockIdx.y * BM, col0 = blockIdx.x * BN;
    int tx = tid & 15, ty = tid >> 4;

    int a_m  = tid >> 1;
    int a_kq = (tid & 1) * 16;
    int am = row0 + a_m;
    const float* Ap = nullptr;
    if (am < M) {
        if (MODE == 0) {
            int s = am >> 4, b = am & 15;
            Ap = Asrc + ((size_t)b * SEQ + s) * EMB;
        } else if (MODE == 1) {
            int t = am >> 4, b = am & 15;
            Ap = Asrc + (size_t)toks[b * 100 + t] * EMB;
        } else {
            Ap = g_Hs + (size_t)am * HID;
        }
    }
    int b_n  = tid >> 1;
    int b_kq = (tid & 1) * 16;
    int wn = col0 + b_n;
    const float* Wp = (wn < N) ? (W + (size_t)wn * ldw) : nullptr;

    ull acc[4][8];
    #pragma unroll
    for (int ip = 0; ip < 4; ip++)
        #pragma unroll
        for (int j = 0; j < 8; j++) acc[ip][j] = 0ull;

    float4 rA[4], rB[4];
    #pragma unroll
    for (int q = 0; q < 4; q++) {
        rA[q] = Ap ? *(const float4*)(Ap + a_kq + q * 4) : make_float4(0.f, 0.f, 0.f, 0.f);
        rB[q] = Wp ? *(const float4*)(Wp + b_kq + q * 4) : make_float4(0.f, 0.f, 0.f, 0.f);
    }

    int T = K / BK;
    for (int t = 0; t < T; t++) {
        __syncthreads();
        #pragma unroll
        for (int q = 0; q < 4; q++) {
            int ka = a_kq + q * 4;
            As[(ka + 0) * BM + a_m] = rA[q].x;
            As[(ka + 1) * BM + a_m] = rA[q].y;
            As[(ka + 2) * BM + a_m] = rA[q].z;
            As[(ka + 3) * BM + a_m] = rA[q].w;
            int kb = b_kq + q * 4;
            Bs[(kb + 0) * BN + b_n] = dup2(rB[q].x);
            Bs[(kb + 1) * BN + b_n] = dup2(rB[q].y);
            Bs[(kb + 2) * BN + b_n] = dup2(rB[q].z);
            Bs[(kb + 3) * BN + b_n] = dup2(rB[q].w);
        }
        __syncthreads();
        if (t + 1 < T) {
            int k0 = (t + 1) * BK;
            #pragma unroll
            for (int q = 0; q < 4; q++) {
                rA[q] = Ap ? *(const float4*)(Ap + k0 + a_kq + q * 4) : make_float4(0.f, 0.f, 0.f, 0.f);
                rB[q] = Wp ? *(const float4*)(Wp + k0 + b_kq + q * 4) : make_float4(0.f, 0.f, 0.f, 0.f);
            }
        }
        #pragma unroll 8
        for (int kk = 0; kk < BK; kk++) {
            F4U a0, a1;
            a0.f = *(const float4*)&As[kk * BM + ty * 8];
            a1.f = *(const float4*)&As[kk * BM + ty * 8 + 4];
            ull ap[4] = {a0.u[0], a0.u[1], a1.u[0], a1.u[1]};
            const ull* bp = Bs + kk * BN + tx * 8;
            ulonglong2 q0 = *(const ulonglong2*)(bp);
            ulonglong2 q1 = *(const ulonglong2*)(bp + 2);
            ulonglong2 q2 = *(const ulonglong2*)(bp + 4);
            ulonglong2 q3 = *(const ulonglong2*)(bp + 6);
            ull bb[8] = {q0.x, q0.y, q1.x, q1.y, q2.x, q2.y, q3.x, q3.y};
            #pragma unroll
            for (int ip = 0; ip < 4; ip++)
                #pragma unroll
                for (int j = 0; j < 8; j++)
                    acc[ip][j] = fma2(ap[ip], bb[j], acc[ip][j]);
        }
    }

    #pragma unroll
    for (int ip = 0; ip < 4; ip++) {
        int m0 = row0 + ty * 8 + ip * 2;
        #pragma unroll
        for (int j = 0; j < 8; j++) {
            int n = col0 + tx * 8 + j;
            if (n >= N) continue;
            float2 v = unp2(acc[ip][j]);
            #pragma unroll
            for (int h = 0; h < 2; h++) {
                int m = m0 + h;
                if (m >= M) continue;
                float val = (h == 0) ? v.x : v.y;
                int b = m & 15, t = m >> 4;
                if (MODE == 0) {
                    val += bias[n];
                    float* dst = sel ? g_gi_b : g_gi_f;
                    dst[(size_t)m * 1536 + n] = val;
                } else if (MODE == 1) {
                    val += g_ctxgi[b * 1536 + n];
                    g_gid[(size_t)m * 1536 + n] = val;
                } else {
                    val += g_base[(size_t)b * VOC + n];
                    Cout[((size_t)b * TM1 + t) * VOC + n] = val;
                }
            }
        }
    }
}

// ---------------- encoder GRU: ONE time-step per launch --------------------
// 128 blocks: blocks 0-63 = forward dir, 64-127 = backward dir.
// Kernel-boundary = global sync; no software barrier, no persistence.
__global__ void __launch_bounds__(128) enc_step(
    const float* __restrict__ Whh_f, const float* __restrict__ bhh_f,
    const float* __restrict__ Whh_b, const float* __restrict__ bhh_b, int step)
{
    __shared__ float hs[8192];   // h, layout (i>>2)*64 + b*4 + (i&3)
    int dir = blockIdx.x >> 6, blk = blockIdx.x & 63;
    int tid = threadIdx.x, b = tid & 15, il = tid >> 4;   // il 0..7
    int i = blk * 8 + il;

    const float* Whh = dir ? Whh_b : Whh_f;
    const float* bhh = dir ? bhh_b : bhh_f;
    const float* gi  = dir ? g_gi_b : g_gi_f;
    float* hg = dir ? g_hb : g_hf;

    if (step == 0) {
        for (int x = tid; x < 2048; x += 128)
            ((float4*)hs)[x] = make_float4(0.f, 0.f, 0.f, 0.f);
    } else {
        for (int x = tid; x < 2048; x += 128)
            ((float4*)hs)[x] = __ldg(((const float4*)hg) + x);
    }
    __syncthreads();

    int s = dir ? (SEQ - 1 - step) : step;
    const float* wr = Whh + (size_t)i * 512;
    const float* wz = Whh + (size_t)(i + 512) * 512;
    const float* wn = Whh + (size_t)(i + 1024) * 512;

    ull ar = 0ull, az = 0ull, an = 0ull;
    #pragma unroll 4
    for (int k = 0; k < 512; k += 4) {
        F4U h4; h4.f = *(const float4*)&hs[(k >> 2) * 64 + b * 4];
        F4U w;
        w.f = __ldg((const float4*)(wr + k));
        ar = fma2(w.u[0], h4.u[0], ar); ar = fma2(w.u[1], h4.u[1], ar);
        w.f = __ldg((const float4*)(wz + k));
        az = fma2(w.u[0], h4.u[0], az); az = fma2(w.u[1], h4.u[1], az);
        w.f = __ldg((const float4*)(wn + k));
        an = fma2(w.u[0], h4.u[0], an); an = fma2(w.u[1], h4.u[1], an);
    }
    const float* gp = gi + ((size_t)s * 16 + b) * 1536 + i;
    float r = sigmoidf_(gp[0]    + hsum2(ar) + bhh[i]);
    float z = sigmoidf_(gp[512]  + hsum2(az) + bhh[i + 512]);
    float n = tanhf(gp[1024] + r * (hsum2(an) + bhh[i + 1024]));
    int hidx = (i >> 2) * 64 + b * 4 + (i & 3);
    float hnew = (1.f - z) * n + z * hs[hidx];
    hg[hidx] = hnew;
    g_enc_out[((size_t)b * SEQ + s) * 1024 + dir * 512 + i] = hnew;
}

// ---------------- decoder init: h0 = hf + hb -------------------------------
__global__ void dec_init() {
    int x = blockIdx.x * 256 + threadIdx.x;
    if (x < 8192) g_hd[x] = g_hf[x] + g_hb[x];
}

// ---------------- decoder GRU: ONE time-step per launch --------------------
__global__ void __launch_bounds__(128) dec_step(const float* __restrict__ Whh,
                                                const float* __restrict__ bhh, int t) {
    __shared__ float hs[8192];
    int blk = blockIdx.x;
    int tid = threadIdx.x, b = tid & 15, il = tid >> 4;
    int i = blk * 8 + il;

    for (int x = tid; x < 2048; x += 128)
        ((float4*)hs)[x] = __ldg(((const float4*)g_hd) + x);
    __syncthreads();

    const float* wr = Whh + (size_t)i * 512;
    const float* wz = Whh + (size_t)(i + 512) * 512;
    const float* wn = Whh + (size_t)(i + 1024) * 512;

    ull ar = 0ull, az = 0ull, an = 0ull;
    #pragma unroll 4
    for (int k = 0; k < 512; k += 4) {
        F4U h4; h4.f = *(const float4*)&hs[(k >> 2) * 64 + b * 4];
        F4U w;
        w.f = __ldg((const float4*)(wr + k));
        ar = fma2(w.u[0], h4.u[0], ar); ar = fma2(w.u[1], h4.u[1], ar);
        w.f = __ldg((const float4*)(wz + k));
        az = fma2(w.u[0], h4.u[0], az); az = fma2(w.u[1], h4.u[1], az);
        w.f = __ldg((const float4*)(wn + k));
        an = fma2(w.u[0], h4.u[0], an); an = fma2(w.u[1], h4.u[1], an);
    }
    const float* gp = g_gid + ((size_t)t * 16 + b) * 1536 + i;
    float r = sigmoidf_(gp[0]    + hsum2(ar) + bhh[i]);
    float z = sigmoidf_(gp[512]  + hsum2(az) + bhh[i + 512]);
    float n = tanhf(gp[1024] + r * (hsum2(an) + bhh[i + 1024]));
    int hidx = (i >> 2) * 64 + b * 4 + (i & 3);
    float hnew = (1.f - z) * n + z * hs[hidx];
    g_hd[hidx] = hnew;
    g_Hs[((size_t)t * 16 + b) * HID + i] = hnew;
}

// ---------------- attention: scores + softmax + ctx2h (once) ---------------
__global__ void attn_kernel(const int* __restrict__ amask) {
    int b = blockIdx.x, tid = threadIdx.x;
    __shared__ float vs[1024];
    __shared__ float ws[SEQ];
    __shared__ float red[16];
    for (int x = tid; x < 1024; x += 256) vs[x] = g_v[x];
    __syncthreads();

    const float* row = g_enc_out + ((size_t)b * SEQ + tid) * 1024;
    ull acc2 = 0ull;
    for (int k = 0; k < 1024; k += 4) {
        F4U e, v;
        e.f = *(const float4*)(row + k);
        v.f = *(const float4*)(vs + k);
        acc2 = fma2(e.u[0], v.u[0], acc2);
        acc2 = fma2(e.u[1], v.u[1], acc2);
    }
    float sc = hsum2(acc2) + g_c0;
    if (amask[b * SEQ + tid] == 0) sc = -1e9f;

    float m = sc;
    #pragma unroll
    for (int o = 16; o; o >>= 1) m = fmaxf(m, __shfl_xor_sync(0xffffffffu, m, o));
    if ((tid & 31) == 0) red[tid >> 5] = m;
    __syncthreads();
    if (tid < 32) {
        float t = (tid < 8) ? red[tid] : -3.4e38f;
        #pragma unroll
        for (int o = 4; o; o >>= 1) t = fmaxf(t, __shfl_xor_sync(0xffffffffu, t, o));
        if (tid == 0) red[0] = t;
    }
    __syncthreads();
    float mx = red[0];
    float e = expf(sc - mx);
    float sm = e;
    #pragma unroll
    for (int o = 16; o; o >>= 1) sm += __shfl_xor_sync(0xffffffffu, sm, o);
    __syncthreads();
    if ((tid & 31) == 0) red[8 + (tid >> 5)] = sm;
    __syncthreads();
    if (tid < 32) {
        float t = (tid < 8) ? red[8 + tid] : 0.f;
        #pragma unroll
        for (int o = 4; o; o >>= 1) t += __shfl_xor_sync(0xffffffffu, t, o);
        if (tid == 0) red[0] = t;
    }
    __syncthreads();
    float total = red[0];
    ws[tid] = e / total;
    __syncthreads();

    #pragma unroll
    for (int kk = 0; kk < 4; kk++) {
        int k = tid + kk * 256;
        float a2 = 0.f;
        for (int s = 0; s < SEQ; s++)
            a2 += ws[s] * g_enc_out[((size_t)b * SEQ + s) * 1024 + k];
        g_ctx2h[b * 1024 + k] = a2;
    }
}

// ---------------- small GEMMs: proj / ctx_gi / base ------------------------
__global__ void small_mm(const float* __restrict__ W, const float* __restrict__ bias,
                         int mode, int N, int K, int ldw, int koff) {
    int idx = blockIdx.x * 256 + threadIdx.x;
    if (idx >= 16 * N) return;
    int b = idx & 15, n = idx >> 4;
    const float* A = (mode == 0) ? (g_ctx2h + b * 1024) : (g_ctx + b * 512);
    const float* w = W + (size_t)n * ldw + koff;
    ull acc2 = 0ull;
    for (int k = 0; k < K; k += 4) {
        F4U av, wv;
        av.f = *(const float4*)(A + k);
        wv.f = *(const float4*)(w + k);
        acc2 = fma2(av.u[0], wv.u[0], acc2);
        acc2 = fma2(av.u[1], wv.u[1], acc2);
    }
    float acc = hsum2(acc2) + bias[n];
    if (mode == 0)      g_ctx[b * 512 + n] = acc;
    else if (mode == 1) g_ctxgi[b * 1536 + n] = acc;
    else                g_base[(size_t)b * VOC + n] = acc;
}

// ---------------- launch -------------------------------------------------
extern "C" void kernel_launch(void* const* d_in, const int* in_sizes, int n_in,
                              void* d_out, int out_size) {
    const float* bert   = (const float*)d_in[0];
    const int*   amask  = (const int*)d_in[1];
    const int*   ids    = (const int*)d_in[2];
    const float* emb    = (const float*)d_in[3];
    const float* eWih_f = (const float*)d_in[4];
    const float* eWhh_f = (const float*)d_in[5];
    const float* ebih_f = (const float*)d_in[6];
    const float* ebhh_f = (const float*)d_in[7];
    const float* eWih_b = (const float*)d_in[8];
    const float* eWhh_b = (const float*)d_in[9];
    const float* ebih_b = (const float*)d_in[10];
    const float* ebhh_b = (const float*)d_in[11];
    const float* dWih   = (const float*)d_in[12];
    const float* dWhh   = (const float*)d_in[13];
    const float* dbih   = (const float*)d_in[14];
    const float* dbhh   = (const float*)d_in[15];
    const float* attn_W = (const float*)d_in[16];
    const float* attn_b = (const float*)d_in[17];
    const float* comb_W = (const float*)d_in[18];
    const float* comb_b = (const float*)d_in[19];
    const float* proj_W = (const float*)d_in[20];
    const float* proj_b = (const float*)d_in[21];
    const float* out_W  = (const float*)d_in[22];
    const float* out_b  = (const float*)d_in[23];
    float* out = (float*)d_out;

    static int attr_done = 0;
    if (!attr_done) {
        cudaFuncSetAttribute(sgemm2<0>, cudaFuncAttributeMaxDynamicSharedMemorySize, 49152);
        cudaFuncSetAttribute(sgemm2<1>, cudaFuncAttributeMaxDynamicSharedMemorySize, 49152);
        cudaFuncSetAttribute(sgemm2<2>, cudaFuncAttributeMaxDynamicSharedMemorySize, 49152);
        attr_done = 1;
    }

    const int SGEMM_SMEM = 49152;

    // attention folding
    fold_kernel<<<4, 256>>>(attn_W, attn_b, comb_W, comb_b);

    // encoder input gates
    sgemm2<0><<<dim3(12, 32), 256, SGEMM_SMEM>>>(bert, eWih_f, 768, ebih_f, nullptr, nullptr, 0, 4096, 1536, 768);
    sgemm2<0><<<dim3(12, 32), 256, SGEMM_SMEM>>>(bert, eWih_b, 768, ebih_b, nullptr, nullptr, 1, 4096, 1536, 768);

    // bidirectional encoder scan: one launch per step (kernel boundary = sync)
    for (int s = 0; s < SEQ; s++)
        enc_step<<<128, 128>>>(eWhh_f, ebhh_f, eWhh_b, ebhh_b, s);

    // attention (once — h-dependence cancels in softmax)
    attn_kernel<<<16, 256>>>(amask);

    // ctx = ctx2h @ proj_W.T + proj_b
    small_mm<<<32, 256>>>(proj_W, proj_b, 0, 512, 1024, 1024, 0);
    // ctx_gi = ctx @ dec_Wih[:,768:].T + dec_bih
    small_mm<<<96, 256>>>(dWih, dbih, 1, 1536, 512, 1280, 768);

    // decoder input gates: gathered emb rows GEMM + ctx_gi
    sgemm2<1><<<dim3(12, 13), 256, SGEMM_SMEM>>>(emb, dWih, 1280, nullptr, ids, nullptr, 0, 1584, 1536, 768);

    // decoder scan: init + one launch per step
    dec_init<<<32, 256>>>();
    for (int t = 0; t < TM1; t++)
        dec_step<<<64, 128>>>(dWhh, dbhh, t);

    // base = ctx @ out_W[:,512:].T + out_b
    small_mm<<<1908, 256>>>(out_W, out_b, 2, VOC, 512, 1024, 512);

    // logits = Hs @ out_W[:,:512].T + base  ->  out[b][t][v]
    sgemm2<2><<<dim3(239, 13), 256, SGEMM_SMEM>>>(nullptr, out_W, 1024, nullptr, nullptr, out, 0, 1584, VOC, 512);
}

// round 6
// speedup vs baseline: 1.4796x; 1.4796x over previous
#include <cuda_runtime.h>
#include <math.h>

typedef unsigned long long ull;

// Problem constants
#define SEQ   256
#define BSZ   16
#define HID   512
#define EMB   768
#define VOC   30522
#define TM1   99

// ---------------- scratch (device globals; no allocations) ----------------
__device__ float g_gi_f[SEQ*BSZ*1536];     // encoder fwd gi
__device__ float g_gi_b[SEQ*BSZ*1536];     // encoder bwd gi
__device__ float g_enc_out[BSZ*SEQ*1024];  // [b][s][1024] concat(fwd,bwd)
__device__ float g_hf[HID*BSZ];            // h in hs4 layout: (i>>2)*64 + b*4 + (i&3)
__device__ float g_hb[HID*BSZ];
__device__ float g_hd[HID*BSZ];
__device__ float g_v[1024];                // folded attention vector (enc part)
__device__ float g_c0;                     // folded attention scalar
__device__ float g_ctx2h[BSZ*1024];
__device__ float g_ctx[BSZ*HID];
__device__ float g_ctxgi[BSZ*1536];        // ctx@dec_Wih[:,768:].T + dec_bih
__device__ float g_gid[TM1*BSZ*1536];      // decoder gi
__device__ float g_Hs[TM1*BSZ*HID];        // decoder hidden states row-major [(t*16+b)][512]
__device__ float g_base[BSZ*VOC];          // ctx@out_W[:,512:].T + out_b
__device__ unsigned int g_bar_count[4];

// ---------------- f32x2 helpers -------------------------------------------
__device__ __forceinline__ ull fma2(ull a, ull b, ull c) {
    ull d;
    asm("fma.rn.f32x2 %0, %1, %2, %3;" : "=l"(d) : "l"(a), "l"(b), "l"(c));
    return d;
}
__device__ __forceinline__ ull add2(ull a, ull b) {
    ull d;
    asm("add.rn.f32x2 %0, %1, %2;" : "=l"(d) : "l"(a), "l"(b));
    return d;
}
__device__ __forceinline__ ull dup2(float x) {
    ull d;
    asm("mov.b64 %0, {%1, %1};" : "=l"(d) : "f"(x));
    return d;
}
__device__ __forceinline__ float hsum2(ull v) {
    float x, y;
    asm("mov.b64 {%0, %1}, %2;" : "=f"(x), "=f"(y) : "l"(v));
    return x + y;
}
__device__ __forceinline__ float2 unp2(ull v) {
    float2 r;
    asm("mov.b64 {%0, %1}, %2;" : "=f"(r.x), "=f"(r.y) : "l"(v));
    return r;
}
union F4U { float4 f; ull u[2]; };

__device__ __forceinline__ float sigmoidf_(float x) { return 1.0f / (1.0f + expf(-x)); }

// barrier: release-RED arrival + acquire polling, all threads sync around it
__device__ __forceinline__ void gbar(int id, unsigned nb, unsigned &target) {
    __syncthreads();
    if (threadIdx.x == 0) {
        __threadfence();                      // order h stores before arrival
        atomicAdd(&g_bar_count[id], 1u);      // result unused -> RED
        target += nb;
        unsigned v;
        do {
            asm volatile("ld.global.acquire.gpu.u32 %0, [%1];"
                         : "=r"(v) : "l"(&g_bar_count[id]) : "memory");
        } while (v < target);
    }
    __syncthreads();
}

// ---------------- fold attention + barrier reset ---------------------------
__global__ void fold_kernel(const float* __restrict__ attn_W, const float* __restrict__ attn_b,
                            const float* __restrict__ comb_W, const float* __restrict__ comb_b) {
    if (blockIdx.x == 0 && threadIdx.x < 4) g_bar_count[threadIdx.x] = 0u;
    int k = blockIdx.x * 256 + threadIdx.x;
    if (k < 1024) {
        float acc = 0.f;
        for (int j = 0; j < 512; j++) acc += comb_W[j] * attn_W[(size_t)j * 1536 + k];
        g_v[k] = acc;
    }
    if (blockIdx.x == 0 && threadIdx.x == 0) {
        float c = comb_b[0];
        for (int j = 0; j < 512; j++) c += comb_W[j] * attn_b[j];
        g_c0 = c;
    }
}

// ---------------- 128x128x32 SGEMM with f32x2 FFMA2: C = A @ W.T -----------
template<int MODE>
__global__ void __launch_bounds__(256) sgemm2(
    const float* __restrict__ Asrc, const float* __restrict__ W, int ldw,
    const float* __restrict__ bias, const int* __restrict__ toks,
    float* __restrict__ Cout, int sel, int M, int N, int K)
{
    const int BM = 128, BN = 128, BK = 32;
    extern __shared__ char smraw[];
    float* As = (float*)smraw;                  // [BK][BM] floats, 16KB
    ull*   Bs = (ull*)(smraw + BK * BM * 4);    // [BK][BN] duplicated pairs, 32KB

    int tid = threadIdx.x;
    int row0 = blockIdx.y * BM, col0 = blockIdx.x * BN;
    int tx = tid & 15, ty = tid >> 4;

    int a_m  = tid >> 1;
    int a_kq = (tid & 1) * 16;
    int am = row0 + a_m;
    const float* Ap = nullptr;
    if (am < M) {
        if (MODE == 0) {
            int s = am >> 4, b = am & 15;
            Ap = Asrc + ((size_t)b * SEQ + s) * EMB;
        } else if (MODE == 1) {
            int t = am >> 4, b = am & 15;
            Ap = Asrc + (size_t)toks[b * 100 + t] * EMB;
        } else {
            Ap = g_Hs + (size_t)am * HID;
        }
    }
    int b_n  = tid >> 1;
    int b_kq = (tid & 1) * 16;
    int wn = col0 + b_n;
    const float* Wp = (wn < N) ? (W + (size_t)wn * ldw) : nullptr;

    ull acc[4][8];
    #pragma unroll
    for (int ip = 0; ip < 4; ip++)
        #pragma unroll
        for (int j = 0; j < 8; j++) acc[ip][j] = 0ull;

    float4 rA[4], rB[4];
    #pragma unroll
    for (int q = 0; q < 4; q++) {
        rA[q] = Ap ? *(const float4*)(Ap + a_kq + q * 4) : make_float4(0.f, 0.f, 0.f, 0.f);
        rB[q] = Wp ? *(const float4*)(Wp + b_kq + q * 4) : make_float4(0.f, 0.f, 0.f, 0.f);
    }

    int T = K / BK;
    for (int t = 0; t < T; t++) {
        __syncthreads();
        #pragma unroll
        for (int q = 0; q < 4; q++) {
            int ka = a_kq + q * 4;
            As[(ka + 0) * BM + a_m] = rA[q].x;
            As[(ka + 1) * BM + a_m] = rA[q].y;
            As[(ka + 2) * BM + a_m] = rA[q].z;
            As[(ka + 3) * BM + a_m] = rA[q].w;
            int kb = b_kq + q * 4;
            Bs[(kb + 0) * BN + b_n] = dup2(rB[q].x);
            Bs[(kb + 1) * BN + b_n] = dup2(rB[q].y);
            Bs[(kb + 2) * BN + b_n] = dup2(rB[q].z);
            Bs[(kb + 3) * BN + b_n] = dup2(rB[q].w);
        }
        __syncthreads();
        if (t + 1 < T) {
            int k0 = (t + 1) * BK;
            #pragma unroll
            for (int q = 0; q < 4; q++) {
                rA[q] = Ap ? *(const float4*)(Ap + k0 + a_kq + q * 4) : make_float4(0.f, 0.f, 0.f, 0.f);
                rB[q] = Wp ? *(const float4*)(Wp + k0 + b_kq + q * 4) : make_float4(0.f, 0.f, 0.f, 0.f);
            }
        }
        #pragma unroll 8
        for (int kk = 0; kk < BK; kk++) {
            F4U a0, a1;
            a0.f = *(const float4*)&As[kk * BM + ty * 8];
            a1.f = *(const float4*)&As[kk * BM + ty * 8 + 4];
            ull ap[4] = {a0.u[0], a0.u[1], a1.u[0], a1.u[1]};
            const ull* bp = Bs + kk * BN + tx * 8;
            ulonglong2 q0 = *(const ulonglong2*)(bp);
            ulonglong2 q1 = *(const ulonglong2*)(bp + 2);
            ulonglong2 q2 = *(const ulonglong2*)(bp + 4);
            ulonglong2 q3 = *(const ulonglong2*)(bp + 6);
            ull bb[8] = {q0.x, q0.y, q1.x, q1.y, q2.x, q2.y, q3.x, q3.y};
            #pragma unroll
            for (int ip = 0; ip < 4; ip++)
                #pragma unroll
                for (int j = 0; j < 8; j++)
                    acc[ip][j] = fma2(ap[ip], bb[j], acc[ip][j]);
        }
    }

    #pragma unroll
    for (int ip = 0; ip < 4; ip++) {
        int m0 = row0 + ty * 8 + ip * 2;
        #pragma unroll
        for (int j = 0; j < 8; j++) {
            int n = col0 + tx * 8 + j;
            if (n >= N) continue;
            float2 v = unp2(acc[ip][j]);
            #pragma unroll
            for (int h = 0; h < 2; h++) {
                int m = m0 + h;
                if (m >= M) continue;
                float val = (h == 0) ? v.x : v.y;
                int b = m & 15, t = m >> 4;
                if (MODE == 0) {
                    val += bias[n];
                    float* dst = sel ? g_gi_b : g_gi_f;
                    dst[(size_t)m * 1536 + n] = val;
                } else if (MODE == 1) {
                    val += g_ctxgi[b * 1536 + n];
                    g_gid[(size_t)m * 1536 + n] = val;
                } else {
                    val += g_base[(size_t)b * VOC + n];
                    Cout[((size_t)b * TM1 + t) * VOC + n] = val;
                }
            }
        }
    }
}

// ---------------- persistent GRU scan core ---------------------------------
// Block layout: 256 threads = 8 warps.
//   warp w: i_local = w & 3, ks_hi = w >> 2
//   lane:   b = lane & 15, ks_lo = lane >> 4
// Each thread: partial dot over k-range [ks*128, ks*128+128), ks = ks_hi*2+ks_lo,
// for 3 gates. Reduce ks_lo via shfl_xor(16), ks_hi via smem.
// Threads < 64 (b2 = tid&15, il2 = tid>>4) do gate math for i = i0+il2.
// smem: Wsm[12][512] (gate-major: row g*4+i_local), hs[8192], red[12][2][16].
struct ScanSmem {
    float Wsm[12 * 512];
    float hs[8192];
    float red[12 * 2 * 16];
};

template<int NSTEPS, int DIRS>
__device__ __forceinline__ void scan_core(
    const float* __restrict__ Whh, const float* __restrict__ bhh,
    const float* __restrict__ gi, float* __restrict__ hg,
    float* __restrict__ hs_init_a, float* __restrict__ hs_init_b,
    int dir, int i0, int bar_id, unsigned nb,
    float* __restrict__ extra_out /* enc_out or Hs */)
{
    extern __shared__ char smraw[];
    ScanSmem* S = (ScanSmem*)smraw;

    int tid = threadIdx.x;
    int warp = tid >> 5, lane = tid & 31;
    int i_local = warp & 3, ks_hi = warp >> 2;
    int b = lane & 15, ks_lo = lane >> 4;
    int k0 = (ks_hi * 2 + ks_lo) * 128;

    // preload weight slice: rows g*4+i_l  <-  Whh[(g*512 + i0 + i_l)][:]
    for (int x = tid; x < 1536; x += 256) {
        int r = x >> 7;                  // 0..11
        int c = (x & 127) * 4;
        int g = r >> 2, i_l = r & 3;
        *(float4*)(S->Wsm + r * 512 + c) =
            __ldg((const float4*)(Whh + ((size_t)(g * 512) + i0 + i_l) * 512 + c));
    }
    // init h
    if (hs_init_a == nullptr) {
        for (int x = tid; x < 2048; x += 256)
            ((float4*)S->hs)[x] = make_float4(0.f, 0.f, 0.f, 0.f);
    } else if (hs_init_b == nullptr) {
        for (int x = tid; x < 2048; x += 256)
            ((float4*)S->hs)[x] = __ldcg(((const float4*)hs_init_a) + x);
    } else {
        for (int x = tid; x < 2048; x += 256) {
            float4 a = __ldcg(((const float4*)hs_init_a) + x);
            float4 c = __ldcg(((const float4*)hs_init_b) + x);
            ((float4*)S->hs)[x] = make_float4(a.x + c.x, a.y + c.y, a.z + c.z, a.w + c.w);
        }
    }
    __syncthreads();

    unsigned target = 0;
    const float* wr = S->Wsm + (0 * 4 + i_local) * 512 + k0;
    const float* wz = S->Wsm + (1 * 4 + i_local) * 512 + k0;
    const float* wn = S->Wsm + (2 * 4 + i_local) * 512 + k0;
    const float* hbase = S->hs + (k0 >> 2) * 64 + b * 4;

    // per-finisher constants (tid < 64)
    int b2 = tid & 15, il2 = (tid >> 4) & 3;
    int i = i0 + il2;
    float bh_r = bhh[i], bh_z = bhh[i + 512], bh_n = bhh[i + 1024];
    int hidx = (i >> 2) * 64 + b2 * 4 + (i & 3);

    for (int step = 0; step < NSTEPS; step++) {
        int s = (DIRS == 2 && dir) ? (NSTEPS - 1 - step) : step;

        // prefetch gi early (independent of h)
        float gv0 = 0.f, gv1 = 0.f, gv2 = 0.f;
        if (tid < 64) {
            const float* gp = gi + ((size_t)s * 16 + b2) * 1536 + i;
            gv0 = __ldg(gp);
            gv1 = __ldg(gp + 512);
            gv2 = __ldg(gp + 1024);
        }

        ull pr = 0ull, pz = 0ull, pn = 0ull;
        #pragma unroll 8
        for (int kq = 0; kq < 32; kq++) {
            F4U h4; h4.f = *(const float4*)(hbase + kq * 64);
            F4U w;
            w.f = *(const float4*)(wr + kq * 4);
            pr = fma2(w.u[0], h4.u[0], pr); pr = fma2(w.u[1], h4.u[1], pr);
            w.f = *(const float4*)(wz + kq * 4);
            pz = fma2(w.u[0], h4.u[0], pz); pz = fma2(w.u[1], h4.u[1], pz);
            w.f = *(const float4*)(wn + kq * 4);
            pn = fma2(w.u[0], h4.u[0], pn); pn = fma2(w.u[1], h4.u[1], pn);
        }
        // reduce ks_lo (lanes 0-15 vs 16-31)
        pr = add2(pr, __shfl_xor_sync(0xffffffffu, pr, 16));
        pz = add2(pz, __shfl_xor_sync(0xffffffffu, pz, 16));
        pn = add2(pn, __shfl_xor_sync(0xffffffffu, pn, 16));
        if (ks_lo == 0) {
            S->red[(0 * 4 + i_local) * 32 + ks_hi * 16 + b] = hsum2(pr);
            S->red[(1 * 4 + i_local) * 32 + ks_hi * 16 + b] = hsum2(pz);
            S->red[(2 * 4 + i_local) * 32 + ks_hi * 16 + b] = hsum2(pn);
        }
        __syncthreads();

        if (tid < 64) {
            float dr = S->red[(0 * 4 + il2) * 32 + b2] + S->red[(0 * 4 + il2) * 32 + 16 + b2];
            float dz = S->red[(1 * 4 + il2) * 32 + b2] + S->red[(1 * 4 + il2) * 32 + 16 + b2];
            float dn = S->red[(2 * 4 + il2) * 32 + b2] + S->red[(2 * 4 + il2) * 32 + 16 + b2];
            float r = sigmoidf_(gv0 + dr + bh_r);
            float z = sigmoidf_(gv1 + dz + bh_z);
            float n = tanhf(gv2 + r * (dn + bh_n));
            float hnew = (1.f - z) * n + z * S->hs[hidx];
            hg[hidx] = hnew;
            if (DIRS == 2)
                extra_out[((size_t)b2 * SEQ + s) * 1024 + dir * 512 + i] = hnew;
            else
                extra_out[((size_t)s * 16 + b2) * 512 + i] = hnew;
        }

        if (step + 1 < NSTEPS) {
            gbar(bar_id, nb, target);
            for (int x = tid; x < 2048; x += 256)
                ((float4*)S->hs)[x] = __ldcg(((const float4*)hg) + x);
            __syncthreads();
        }
    }
}

// encoder: 256 blocks (128 per dir), barrier per dir over 128 blocks
__global__ void __launch_bounds__(256, 2) enc_scan3(
    const float* __restrict__ Whh_f, const float* __restrict__ bhh_f,
    const float* __restrict__ Whh_b, const float* __restrict__ bhh_b)
{
    int dir = blockIdx.x >> 7;
    int blk = blockIdx.x & 127;
    scan_core<SEQ, 2>(dir ? Whh_b : Whh_f, dir ? bhh_b : bhh_f,
                      dir ? g_gi_b : g_gi_f, dir ? g_hb : g_hf,
                      nullptr, nullptr,
                      dir, blk * 4, dir, 128, g_enc_out);
}

// decoder: 128 blocks, barrier id 2
__global__ void __launch_bounds__(256, 2) dec_scan3(const float* __restrict__ Whh,
                                                    const float* __restrict__ bhh)
{
    scan_core<TM1, 1>(Whh, bhh, g_gid, g_hd,
                      g_hf, g_hb,
                      0, blockIdx.x * 4, 2, 128, g_Hs);
}

// ---------------- attention: scores + softmax + ctx2h (once) ---------------
__global__ void attn_kernel(const int* __restrict__ amask) {
    int b = blockIdx.x, tid = threadIdx.x;
    __shared__ float vs[1024];
    __shared__ float ws[SEQ];
    __shared__ float red[16];
    for (int x = tid; x < 1024; x += 256) vs[x] = g_v[x];
    __syncthreads();

    const float* row = g_enc_out + ((size_t)b * SEQ + tid) * 1024;
    ull acc2 = 0ull;
    for (int k = 0; k < 1024; k += 4) {
        F4U e, v;
        e.f = *(const float4*)(row + k);
        v.f = *(const float4*)(vs + k);
        acc2 = fma2(e.u[0], v.u[0], acc2);
        acc2 = fma2(e.u[1], v.u[1], acc2);
    }
    float sc = hsum2(acc2) + g_c0;
    if (amask[b * SEQ + tid] == 0) sc = -1e9f;

    float m = sc;
    #pragma unroll
    for (int o = 16; o; o >>= 1) m = fmaxf(m, __shfl_xor_sync(0xffffffffu, m, o));
    if ((tid & 31) == 0) red[tid >> 5] = m;
    __syncthreads();
    if (tid < 32) {
        float t = (tid < 8) ? red[tid] : -3.4e38f;
        #pragma unroll
        for (int o = 4; o; o >>= 1) t = fmaxf(t, __shfl_xor_sync(0xffffffffu, t, o));
        if (tid == 0) red[0] = t;
    }
    __syncthreads();
    float mx = red[0];
    float e = expf(sc - mx);
    float sm = e;
    #pragma unroll
    for (int o = 16; o; o >>= 1) sm += __shfl_xor_sync(0xffffffffu, sm, o);
    __syncthreads();
    if ((tid & 31) == 0) red[8 + (tid >> 5)] = sm;
    __syncthreads();
    if (tid < 32) {
        float t = (tid < 8) ? red[8 + tid] : 0.f;
        #pragma unroll
        for (int o = 4; o; o >>= 1) t += __shfl_xor_sync(0xffffffffu, t, o);
        if (tid == 0) red[0] = t;
    }
    __syncthreads();
    float total = red[0];
    ws[tid] = e / total;
    __syncthreads();

    #pragma unroll
    for (int kk = 0; kk < 4; kk++) {
        int k = tid + kk * 256;
        float a2 = 0.f;
        for (int s = 0; s < SEQ; s++)
            a2 += ws[s] * g_enc_out[((size_t)b * SEQ + s) * 1024 + k];
        g_ctx2h[b * 1024 + k] = a2;
    }
}

// ---------------- small GEMMs: proj / ctx_gi / base ------------------------
__global__ void small_mm(const float* __restrict__ W, const float* __restrict__ bias,
                         int mode, int N, int K, int ldw, int koff) {
    int idx = blockIdx.x * 256 + threadIdx.x;
    if (idx >= 16 * N) return;
    int b = idx & 15, n = idx >> 4;
    const float* A = (mode == 0) ? (g_ctx2h + b * 1024) : (g_ctx + b * 512);
    const float* w = W + (size_t)n * ldw + koff;
    ull acc2 = 0ull;
    for (int k = 0; k < K; k += 4) {
        F4U av, wv;
        av.f = *(const float4*)(A + k);
        wv.f = *(const float4*)(w + k);
        acc2 = fma2(av.u[0], wv.u[0], acc2);
        acc2 = fma2(av.u[1], wv.u[1], acc2);
    }
    float acc = hsum2(acc2) + bias[n];
    if (mode == 0)      g_ctx[b * 512 + n] = acc;
    else if (mode == 1) g_ctxgi[b * 1536 + n] = acc;
    else                g_base[(size_t)b * VOC + n] = acc;
}

// ---------------- launch -------------------------------------------------
extern "C" void kernel_launch(void* const* d_in, const int* in_sizes, int n_in,
                              void* d_out, int out_size) {
    const float* bert   = (const float*)d_in[0];
    const int*   amask  = (const int*)d_in[1];
    const int*   ids    = (const int*)d_in[2];
    const float* emb    = (const float*)d_in[3];
    const float* eWih_f = (const float*)d_in[4];
    const float* eWhh_f = (const float*)d_in[5];
    const float* ebih_f = (const float*)d_in[6];
    const float* ebhh_f = (const float*)d_in[7];
    const float* eWih_b = (const float*)d_in[8];
    const float* eWhh_b = (const float*)d_in[9];
    const float* ebih_b = (const float*)d_in[10];
    const float* ebhh_b = (const float*)d_in[11];
    const float* dWih   = (const float*)d_in[12];
    const float* dWhh   = (const float*)d_in[13];
    const float* dbih   = (const float*)d_in[14];
    const float* dbhh   = (const float*)d_in[15];
    const float* attn_W = (const float*)d_in[16];
    const float* attn_b = (const float*)d_in[17];
    const float* comb_W = (const float*)d_in[18];
    const float* comb_b = (const float*)d_in[19];
    const float* proj_W = (const float*)d_in[20];
    const float* proj_b = (const float*)d_in[21];
    const float* out_W  = (const float*)d_in[22];
    const float* out_b  = (const float*)d_in[23];
    float* out = (float*)d_out;

    const int SGEMM_SMEM = 49152;
    const int SCAN_SMEM  = (int)sizeof(ScanSmem);

    static int attr_done = 0;
    if (!attr_done) {
        cudaFuncSetAttribute(sgemm2<0>, cudaFuncAttributeMaxDynamicSharedMemorySize, SGEMM_SMEM);
        cudaFuncSetAttribute(sgemm2<1>, cudaFuncAttributeMaxDynamicSharedMemorySize, SGEMM_SMEM);
        cudaFuncSetAttribute(sgemm2<2>, cudaFuncAttributeMaxDynamicSharedMemorySize, SGEMM_SMEM);
        cudaFuncSetAttribute(enc_scan3, cudaFuncAttributeMaxDynamicSharedMemorySize, SCAN_SMEM);
        cudaFuncSetAttribute(dec_scan3, cudaFuncAttributeMaxDynamicSharedMemorySize, SCAN_SMEM);
        attr_done = 1;
    }

    // attention folding + barrier counter reset
    fold_kernel<<<4, 256>>>(attn_W, attn_b, comb_W, comb_b);

    // encoder input gates
    sgemm2<0><<<dim3(12, 32), 256, SGEMM_SMEM>>>(bert, eWih_f, 768, ebih_f, nullptr, nullptr, 0, 4096, 1536, 768);
    sgemm2<0><<<dim3(12, 32), 256, SGEMM_SMEM>>>(bert, eWih_b, 768, ebih_b, nullptr, nullptr, 1, 4096, 1536, 768);

    // bidirectional encoder scan (persistent, 256 blocks, split-k)
    enc_scan3<<<256, 256, SCAN_SMEM>>>(eWhh_f, ebhh_f, eWhh_b, ebhh_b);

    // attention (once — h-dependence cancels in softmax)
    attn_kernel<<<16, 256>>>(amask);

    // ctx = ctx2h @ proj_W.T + proj_b
    small_mm<<<32, 256>>>(proj_W, proj_b, 0, 512, 1024, 1024, 0);
    // ctx_gi = ctx @ dec_Wih[:,768:].T + dec_bih
    small_mm<<<96, 256>>>(dWih, dbih, 1, 1536, 512, 1280, 768);

    // decoder input gates: gathered emb rows GEMM + ctx_gi
    sgemm2<1><<<dim3(12, 13), 256, SGEMM_SMEM>>>(emb, dWih, 1280, nullptr, ids, nullptr, 0, 1584, 1536, 768);

    // decoder scan (persistent, 128 blocks, split-k); h0 = hf + hb computed in-kernel
    dec_scan3<<<128, 256, SCAN_SMEM>>>(dWhh, dbhh);

    // base = ctx @ out_W[:,512:].T + out_b
    small_mm<<<1908, 256>>>(out_W, out_b, 2, VOC, 512, 1024, 512);

    // logits = Hs @ out_W[:,:512].T + base  ->  out[b][t][v]
    sgemm2<2><<<dim3(239, 13), 256, SGEMM_SMEM>>>(nullptr, out_W, 1024, nullptr, nullptr, out, 0, 1584, VOC, 512);
}